// round 13
// baseline (speedup 1.0000x reference)
#include <cuda_runtime.h>

#define Bb 8
#define Tt 2048
#define Cc 4096
#define Uu 200
#define NEGF (-1e30f)
#define LOG2E 1.4426950408889634f
#define LN2   0.6931471805599453f

#define NW    4      // warps per block (one per SMSP)
#define UW    50     // u-range per warp
#define GG    4      // fused pairs per group
#define RING  32     // boundary ring depth (float2 slots)
#define NPAIR 1023   // pair p covers rows t=2p+1, 2p+2
#define NGM   255    // full groups in main loop (pairs 0..1019)
#define PSTR  1024   // floats per (b,pair): 4 warps * 32 lanes * 8
#define NLN   25     // active lanes per warp

// Scratch: lpt2 [B,T,U] 13.1MB + fused weights 33.5MB (log2 domain).
__device__ float g_lpt[Bb * Tt * Uu];
__device__ float g_W[(size_t)Bb * 1024 * PSTR];   // [b][pair(pad1024)][w*32+lane][8]
__device__ float g_final[Bb];
__device__ int   g_pad;

__device__ __forceinline__ float ex2f(float x) {
    float r; asm("ex2.approx.f32 %0, %1;" : "=f"(r) : "f"(x)); return r;
}
__device__ __forceinline__ float lg2f(float x) {
    float r; asm("lg2.approx.f32 %0, %1;" : "=f"(r) : "f"(x)); return r;
}
__device__ __forceinline__ float lg2add(float x, float y) {
    const float m = fmaxf(x, y);
    return m + lg2f(1.0f + ex2f(-fabsf(x - y)));
}
__device__ __forceinline__ float lse3(float x, float y, float z) {
    const float m = fmaxf(fmaxf(x, y), z);
    const float s = ex2f(x - m) + ex2f(y - m) + ex2f(z - m);
    return m + lg2f(s);
}
__device__ __forceinline__ void cp16(unsigned dst_smem, const void* src) {
    asm volatile("cp.async.ca.shared.global [%0], [%1], 16;"
                 :: "r"(dst_smem), "l"(src));
}

// ---------------------------------------------------------------------------
// Kernel 1: lse + gather, log2 domain. (HBM-bound ~55us.)
// ---------------------------------------------------------------------------
__global__ __launch_bounds__(256) void lpt_kernel(const float* __restrict__ inp,
                                                  const int* __restrict__ t32) {
    const int r = blockIdx.x;
    const int b = r >> 11;             // T = 2048
    const int tid = threadIdx.x;
    const float* __restrict__ row = inp + (size_t)r * Cc;
    const float4* __restrict__ row4 = (const float4*)row;

    float4 v[4];
    float m = NEGF;
    #pragma unroll
    for (int i = 0; i < 4; i++) {
        v[i] = row4[tid + 256 * i];
        m = fmaxf(m, fmaxf(fmaxf(v[i].x, v[i].y), fmaxf(v[i].z, v[i].w)));
    }

    __shared__ float s_red[32];
    #pragma unroll
    for (int off = 16; off; off >>= 1) m = fmaxf(m, __shfl_xor_sync(0xFFFFFFFFu, m, off));
    if ((tid & 31) == 0) s_red[tid >> 5] = m;
    __syncthreads();
    if (tid < 32) {
        float mm = (tid < 8) ? s_red[tid] : NEGF;
        #pragma unroll
        for (int off = 4; off; off >>= 1) mm = fmaxf(mm, __shfl_xor_sync(0xFFFFFFFFu, mm, off));
        if (tid == 0) s_red[0] = mm;
    }
    __syncthreads();
    m = s_red[0];

    float s = 0.f;
    #pragma unroll
    for (int i = 0; i < 4; i++) {
        s += __expf(v[i].x - m) + __expf(v[i].y - m) + __expf(v[i].z - m) + __expf(v[i].w - m);
    }
    #pragma unroll
    for (int off = 16; off; off >>= 1) s += __shfl_xor_sync(0xFFFFFFFFu, s, off);
    __shared__ float s_sum[8];
    if ((tid & 31) == 0) s_sum[tid >> 5] = s;
    __syncthreads();
    if (tid == 0) {
        float tot = 0.f;
        #pragma unroll
        for (int i = 0; i < 8; i++) tot += s_sum[i];
        s_red[0] = m + __logf(tot);
    }
    __syncthreads();
    const float lse = s_red[0];

    if (tid < Uu) {
        const int probe = t32[1] | t32[3] | t32[5] | t32[7] |
                          t32[9] | t32[11] | t32[13] | t32[15];
        const int base = b * Uu + tid;
        const int c = (probe == 0) ? t32[2 * base] : t32[base];
        g_lpt[(size_t)r * Uu + tid] = (row[c] - lse) * LOG2E;
    }
}

// ---------------------------------------------------------------------------
// Kernel 1b: fused 2-step weights (pair p: rows t1=2p+1, t2=2p+2):
//   W0=l[t2,u]+l[t1,u]  W1=l[t2,u]+lg2add(l[t1,u],l[t1,u-1])  W2=l[t2,u]+l[t1,u-1]
// Lane slot (w*32+j), layout [8]: {W0a,W0b,W1a,W1b,W2a,W2b,-,-} for u=2jg,2jg+1.
// ---------------------------------------------------------------------------
__global__ __launch_bounds__(256) void wgt_kernel() {
    const int b = blockIdx.y;
    const int p = blockIdx.x;                        // 0..NPAIR-1
    const int u = threadIdx.x;
    const int t1 = 2 * p + 1;
    __shared__ float r1[Uu], r2[Uu];
    const float* __restrict__ L = g_lpt + ((size_t)b * Tt + t1) * Uu;
    if (u < Uu) { r1[u] = L[u]; r2[u] = L[Uu + u]; }
    __syncthreads();
    if (u < Uu) {
        const float a  = r1[u];
        const float am = (u == 0) ? NEGF : r1[u - 1];
        const float c  = r2[u];
        const int jg = u >> 1;
        const int w  = jg / 25;
        const int j  = jg - 25 * w;
        float* dst = g_W + ((size_t)b * 1024 + p) * PSTR + (w * 32 + j) * 8;
        const int half = u & 1;
        dst[0 + half] = c + a;
        dst[2 + half] = c + lg2add(a, am);
        dst[4 + half] = c + am;
    }
}

// ---------------------------------------------------------------------------
// Kernel 2: fused alpha recursion, 3-stage cp.async pipeline, branch-free
// main loop (ramp-in/ramp-out barrier pattern), bulk-hoisted smem loads.
// 8 blocks (one batch); 4 time-skewed warps; lane j owns u = 50w+2j, +1.
// ---------------------------------------------------------------------------
__global__ __launch_bounds__(128) void alpha_kernel() {
    const int b    = blockIdx.x;
    const int w    = threadIdx.x >> 5;
    const int lane = threadIdx.x & 31;
    const int li   = (lane < NLN) ? lane : (NLN - 1);      // clamped read index
    const float* __restrict__ Wpair0 =
        g_W + (size_t)b * 1024 * PSTR + (w * 32 + lane) * 8;   // + p*PSTR
    const float* __restrict__ Lb =
        g_lpt + (size_t)b * Tt * Uu + w * UW + 2 * li;
    const bool wr = (lane == 24) && (w < NW - 1);

    __shared__ float  st[3][NW][GG][NLN][8];         // 38,400 B staging
    __shared__ float2 ring[NW][RING];                // 1,024 B
    for (int i = threadIdx.x; i < NW * RING; i += 128)
        ((float2*)ring)[i] = make_float2(NEGF, NEGF);
    __syncthreads();

    float a0 = NEGF, a1 = NEGF;
    if (w == 0 && lane == 0) a0 = Lb[0];             // alpha[0,0]

    // per-lane async batch issue: 4 pairs of group m -> stage m%3
    #define ISSUE(mi)                                                         \
    {                                                                         \
        const int _m = (mi);                                                  \
        const int _si = _m % 3;                                               \
        if (lane < NLN) {                                                     \
            const float* _src = Wpair0 + (size_t)(4 * _m) * PSTR;             \
            _Pragma("unroll")                                                 \
            for (int _s = 0; _s < GG; _s++) {                                 \
                unsigned _d = (unsigned)__cvta_generic_to_shared(             \
                    &st[_si][w][_s][lane][0]);                                \
                cp16(_d, _src);                                               \
                cp16(_d + 16, _src + 4);                                      \
                _src += PSTR;                                                 \
            }                                                                 \
        }                                                                     \
        asm volatile("cp.async.commit_group;");                               \
    }

    ISSUE(0); ISSUE(1);

    // ramp-in: warp w idles through the first w wall-groups
    for (int g = 0; g < w; g++) __syncthreads();

    for (int m = 0; m < NGM; m++) {
        asm volatile("cp.async.wait_group 1;");      // batch m resident
        const int si = m % 3;

        // bulk-hoist: staged weights + ring boundary values -> registers
        float4 WA[GG], WB[GG];
        float2 rv[GG];
        #pragma unroll
        for (int s = 0; s < GG; s++) {
            WA[s] = *(const float4*)&st[si][w][s][li][0];
            WB[s] = *(const float4*)&st[si][w][s][li][4];
        }
        if (lane == 0 && w > 0) {
            #pragma unroll
            for (int s = 0; s < GG; s++)
                rv[s] = ring[w - 1][(4 * m - 1 + s) & (RING - 1)];
        } else {
            #pragma unroll
            for (int s = 0; s < GG; s++) rv[s] = make_float2(NEGF, NEGF);
        }

        // issue batch m+2 now so the copy overlaps this group's chains
        const int mn = (m + 2 < NGM) ? (m + 2) : (NGM - 1);
        ISSUE(mn);

        #pragma unroll
        for (int s = 0; s < GG; s++) {
            const float sh1 = __shfl_up_sync(0xFFFFFFFFu, a1, 1);
            const float sh0 = __shfl_up_sync(0xFFFFFFFFu, a0, 1);
            const float La1 = (lane == 0) ? rv[s].y : sh1;   // a[u0-1]
            const float La0 = (lane == 0) ? rv[s].x : sh0;   // a[u0-2]
            const float x0 = WA[s].x + a0, y0 = WA[s].z + La1, z0 = WB[s].x + La0;
            const float x1 = WA[s].y + a1, y1 = WA[s].w + a0,  z1 = WB[s].y + La1;
            a0 = lse3(x0, y0, z0);
            a1 = lse3(x1, y1, z1);
            if (wr) ring[w][(4 * m + s) & (RING - 1)] = make_float2(a0, a1);
        }
        __syncthreads();
    }

    // ramp-out: pad barrier count so all threads hit NGM + NW - 1 barriers
    for (int g = 0; g < NW - 1 - w; g++) __syncthreads();

    // ---- tail: pairs 1020..1022 (direct LDG, prefetched) + plain t=2047 ----
    float4 tw[3][2];
    #pragma unroll
    for (int q = 0; q < 3; q++) {
        const float* src = Wpair0 + (size_t)(1020 + q) * PSTR;
        tw[q][0] = *(const float4*)src;
        tw[q][1] = *(const float4*)(src + 4);
    }
    const float2 cfin = *(const float2*)(Lb + (size_t)2047 * Uu);

    #pragma unroll
    for (int q = 0; q < 3; q++) {
        const int p = 1020 + q;
        float2 rvp = make_float2(NEGF, NEGF);
        if (lane == 0 && w > 0) rvp = ring[w - 1][(p - 1) & (RING - 1)];
        const float sh1 = __shfl_up_sync(0xFFFFFFFFu, a1, 1);
        const float sh0 = __shfl_up_sync(0xFFFFFFFFu, a0, 1);
        const float La1 = (lane == 0) ? rvp.y : sh1;
        const float La0 = (lane == 0) ? rvp.x : sh0;
        const float x0 = tw[q][0].x + a0, y0 = tw[q][0].z + La1, z0 = tw[q][1].x + La0;
        const float x1 = tw[q][0].y + a1, y1 = tw[q][0].w + a0,  z1 = tw[q][1].y + La1;
        a0 = lse3(x0, y0, z0);
        a1 = lse3(x1, y1, z1);
        if (wr) ring[w][p & (RING - 1)] = make_float2(a0, a1);
        __syncthreads();
    }

    {   // final step t = 2047
        const float sh1 = __shfl_up_sync(0xFFFFFFFFu, a1, 1);
        const float La1 = (lane == 0)
            ? ((w > 0) ? ring[w - 1][1022 & (RING - 1)].y : NEGF)
            : sh1;
        const float n1 = cfin.y + lg2add(a1, a0);
        const float n0 = cfin.x + lg2add(a0, La1);
        a0 = n0; a1 = n1;
    }

    if (w == NW - 1 && lane == 24) g_final[b] = a1;  // u=199, t=2047
    #undef ISSUE
}

// ---------------------------------------------------------------------------
// Kernel 3: loss = mean_b(-alpha_final[b]) in natural-log units.
// ---------------------------------------------------------------------------
__global__ void finish_kernel(float* __restrict__ out) {
    float s = 0.f;
    #pragma unroll
    for (int i = 0; i < Bb; i++) s += g_final[i];
    out[0] = -s * (LN2 / Bb);
}

__global__ void pad_kernel() { g_pad = 0; }

extern "C" void kernel_launch(void* const* d_in, const int* in_sizes, int n_in,
                              void* d_out, int out_size) {
    int ii = 0, ti = 1;
    if (n_in >= 2 && in_sizes[0] < in_sizes[1]) { ii = 1; ti = 0; }
    const float* inp = (const float*)d_in[ii];
    const int*   t32 = (const int*)d_in[ti];
    float* out = (float*)d_out;

    // ncu (-s 5 -c 1) lands on launch position 4 -> alpha_kernel.
    pad_kernel<<<1, 1>>>();
    lpt_kernel<<<Bb * Tt, 256>>>(inp, t32);
    wgt_kernel<<<dim3(NPAIR, Bb), 256>>>();
    alpha_kernel<<<Bb, 128>>>();
    finish_kernel<<<1, 1>>>(out);
}

// round 14
// speedup vs baseline: 1.1222x; 1.1222x over previous
#include <cuda_runtime.h>

#define Bb 8
#define Tt 2048
#define Cc 4096
#define Uu 200
#define NEGF (-1e30f)
#define LOG2E 1.4426950408889634f
#define LN2   0.6931471805599453f

#define NW     4      // warps per block (one per SMSP)
#define UW     50     // u-range per warp
#define GG     8      // fused pairs per wall-group
#define RING   32     // boundary ring depth (float2 slots)
#define NPR    1024   // pairs incl. identity pad (real pairs 0..1022, 1023=identity)
#define NGM    128    // wall-groups in main loop (8 pairs each)
#define PSTR   1024   // floats per (b,pair): 4 warps * 32 lane-slots * 8
#define NLN    25     // active lanes per warp
#define ST_FLOATS (3 * NW * GG * NLN * 8)    // 19,200 floats = 76,800 B dynamic smem

// Scratch: lpt2 [B,T,U] 13.1MB + fused weights 33.5MB (log2 domain).
__device__ float g_lpt[Bb * Tt * Uu];
__device__ float g_W[(size_t)Bb * NPR * PSTR];
__device__ float g_final[Bb];
__device__ int   g_pad;

__device__ __forceinline__ float ex2f(float x) {
    float r; asm("ex2.approx.f32 %0, %1;" : "=f"(r) : "f"(x)); return r;
}
__device__ __forceinline__ float lg2f(float x) {
    float r; asm("lg2.approx.f32 %0, %1;" : "=f"(r) : "f"(x)); return r;
}
__device__ __forceinline__ float lg2add(float x, float y) {
    const float m = fmaxf(x, y);
    return m + lg2f(1.0f + ex2f(-fabsf(x - y)));
}
__device__ __forceinline__ float lse3(float x, float y, float z) {
    const float m = fmaxf(fmaxf(x, y), z);
    const float s = ex2f(x - m) + ex2f(y - m) + ex2f(z - m);
    return m + lg2f(s);
}
__device__ __forceinline__ void cp16(unsigned dst_smem, const void* src) {
    asm volatile("cp.async.ca.shared.global [%0], [%1], 16;"
                 :: "r"(dst_smem), "l"(src));
}

// ---------------------------------------------------------------------------
// Kernel 1: lse + gather, log2 domain. (HBM-bound ~55us.)
// ---------------------------------------------------------------------------
__global__ __launch_bounds__(256) void lpt_kernel(const float* __restrict__ inp,
                                                  const int* __restrict__ t32) {
    const int r = blockIdx.x;
    const int b = r >> 11;             // T = 2048
    const int tid = threadIdx.x;
    const float* __restrict__ row = inp + (size_t)r * Cc;
    const float4* __restrict__ row4 = (const float4*)row;

    float4 v[4];
    float m = NEGF;
    #pragma unroll
    for (int i = 0; i < 4; i++) {
        v[i] = row4[tid + 256 * i];
        m = fmaxf(m, fmaxf(fmaxf(v[i].x, v[i].y), fmaxf(v[i].z, v[i].w)));
    }

    __shared__ float s_red[32];
    #pragma unroll
    for (int off = 16; off; off >>= 1) m = fmaxf(m, __shfl_xor_sync(0xFFFFFFFFu, m, off));
    if ((tid & 31) == 0) s_red[tid >> 5] = m;
    __syncthreads();
    if (tid < 32) {
        float mm = (tid < 8) ? s_red[tid] : NEGF;
        #pragma unroll
        for (int off = 4; off; off >>= 1) mm = fmaxf(mm, __shfl_xor_sync(0xFFFFFFFFu, mm, off));
        if (tid == 0) s_red[0] = mm;
    }
    __syncthreads();
    m = s_red[0];

    float s = 0.f;
    #pragma unroll
    for (int i = 0; i < 4; i++) {
        s += __expf(v[i].x - m) + __expf(v[i].y - m) + __expf(v[i].z - m) + __expf(v[i].w - m);
    }
    #pragma unroll
    for (int off = 16; off; off >>= 1) s += __shfl_xor_sync(0xFFFFFFFFu, s, off);
    __shared__ float s_sum[8];
    if ((tid & 31) == 0) s_sum[tid >> 5] = s;
    __syncthreads();
    if (tid == 0) {
        float tot = 0.f;
        #pragma unroll
        for (int i = 0; i < 8; i++) tot += s_sum[i];
        s_red[0] = m + __logf(tot);
    }
    __syncthreads();
    const float lse = s_red[0];

    if (tid < Uu) {
        const int probe = t32[1] | t32[3] | t32[5] | t32[7] |
                          t32[9] | t32[11] | t32[13] | t32[15];
        const int base = b * Uu + tid;
        const int c = (probe == 0) ? t32[2 * base] : t32[base];
        g_lpt[(size_t)r * Uu + tid] = (row[c] - lse) * LOG2E;
    }
}

// ---------------------------------------------------------------------------
// Kernel 1b: fused 2-step weights (pair p: rows t1=2p+1, t2=2p+2):
//   W0=l[t2,u]+l[t1,u]  W1=l[t2,u]+lg2add(l[t1,u],l[t1,u-1])  W2=l[t2,u]+l[t1,u-1]
// Pair 1023 = exact identity (W0=0, W1=W2=NEG): a_new = a.
// Lane slot (w*32+j), layout [8]: {W0a,W0b,W1a,W1b,W2a,W2b,-,-} for u=2jg,2jg+1.
// ---------------------------------------------------------------------------
__global__ __launch_bounds__(256) void wgt_kernel() {
    const int b = blockIdx.y;
    const int p = blockIdx.x;                        // 0..1023
    const int u = threadIdx.x;
    if (u >= Uu) return;
    const int jg = u >> 1;
    const int w  = jg / 25;
    const int j  = jg - 25 * w;
    float* dst = g_W + ((size_t)b * NPR + p) * PSTR + (w * 32 + j) * 8;
    const int half = u & 1;

    if (p == NPR - 1) {                              // identity pad pair
        dst[0 + half] = 0.0f;
        dst[2 + half] = NEGF;
        dst[4 + half] = NEGF;
        return;
    }
    const int t1 = 2 * p + 1;
    __shared__ float r1[Uu], r2[Uu];
    const float* __restrict__ L = g_lpt + ((size_t)b * Tt + t1) * Uu;
    r1[u] = L[u]; r2[u] = L[Uu + u];
    __syncthreads();
    const float a  = r1[u];
    const float am = (u == 0) ? NEGF : r1[u - 1];
    const float c  = r2[u];
    dst[0 + half] = c + a;
    dst[2 + half] = c + lg2add(a, am);
    dst[4 + half] = c + am;
}

// ---------------------------------------------------------------------------
// Kernel 2: fused alpha recursion. 8 pairs per wall-group (131 wall-groups),
// 3-stage cp.async pipeline in DYNAMIC smem, ramp-in/out barrier pattern.
// 8 blocks (one batch); 4 time-skewed warps; lane j owns u = 50w+2j, +1.
// ---------------------------------------------------------------------------
extern __shared__ float g_dyn[];                     // st[3][NW][GG][NLN][8]

__global__ __launch_bounds__(128) void alpha_kernel() {
    const int b    = blockIdx.x;
    const int w    = threadIdx.x >> 5;
    const int lane = threadIdx.x & 31;
    const int li   = (lane < NLN) ? lane : (NLN - 1);
    const float* __restrict__ Wpair0 =
        g_W + (size_t)b * NPR * PSTR + (w * 32 + lane) * 8;    // + p*PSTR
    const float* __restrict__ Lb =
        g_lpt + (size_t)b * Tt * Uu + w * UW + 2 * li;
    const bool wr = (lane == 24) && (w < NW - 1);

    __shared__ float2 ring[NW][RING];                // 1 KB static
    for (int i = threadIdx.x; i < NW * RING; i += 128)
        ((float2*)ring)[i] = make_float2(NEGF, NEGF);
    __syncthreads();

    float a0 = NEGF, a1 = NEGF;
    if (w == 0 && lane == 0) a0 = Lb[0];             // alpha[0,0]

    // staging offset: ((si*NW + w)*GG + s)*NLN*8 + ln*8
    #define STOFF(si, s, ln) ((((si) * NW + w) * GG + (s)) * NLN + (ln)) * 8

    #define ISSUE(mi)                                                         \
    {                                                                         \
        const int _m = (mi);                                                  \
        const int _si = _m % 3;                                               \
        if (lane < NLN) {                                                     \
            const float* _src = Wpair0 + (size_t)(GG * _m) * PSTR;            \
            _Pragma("unroll")                                                 \
            for (int _s = 0; _s < GG; _s++) {                                 \
                unsigned _d = (unsigned)__cvta_generic_to_shared(             \
                    &g_dyn[STOFF(_si, _s, lane)]);                            \
                cp16(_d, _src);                                               \
                cp16(_d + 16, _src + 4);                                      \
                _src += PSTR;                                                 \
            }                                                                 \
        }                                                                     \
        asm volatile("cp.async.commit_group;");                               \
    }

    ISSUE(0); ISSUE(1);

    for (int g = 0; g < w; g++) __syncthreads();     // ramp-in

    for (int m = 0; m < NGM; m++) {
        asm volatile("cp.async.wait_group 1;");      // batch m resident
        const int si = m % 3;
        #pragma unroll
        for (int s = 0; s < GG; s++) {
            const int p = GG * m + s;
            float2 rvp = make_float2(NEGF, NEGF);
            if (lane == 0 && w > 0) rvp = ring[w - 1][(p - 1) & (RING - 1)];
            const float4 wA = *(const float4*)&g_dyn[STOFF(si, s, li)];
            const float4 wB = *(const float4*)&g_dyn[STOFF(si, s, li) + 4];
            const float sh1 = __shfl_up_sync(0xFFFFFFFFu, a1, 1);
            const float sh0 = __shfl_up_sync(0xFFFFFFFFu, a0, 1);
            const float La1 = (lane == 0) ? rvp.y : sh1;   // a[u0-1]
            const float La0 = (lane == 0) ? rvp.x : sh0;   // a[u0-2]
            const float x0 = wA.x + a0, y0 = wA.z + La1, z0 = wB.x + La0;
            const float x1 = wA.y + a1, y1 = wA.w + a0,  z1 = wB.y + La1;
            a0 = lse3(x0, y0, z0);
            a1 = lse3(x1, y1, z1);
            if (wr) ring[w][p & (RING - 1)] = make_float2(a0, a1);
        }
        const int mn = (m + 2 < NGM) ? (m + 2) : (NGM - 1);
        ISSUE(mn);
        __syncthreads();
    }

    for (int g = 0; g < NW - 1 - w; g++) __syncthreads();   // ramp-out

    {   // final plain step t = 2047 (state is at t = 2046)
        const float2 cfin = *(const float2*)(Lb + (size_t)2047 * Uu);
        const float sh1 = __shfl_up_sync(0xFFFFFFFFu, a1, 1);
        const float La1 = (lane == 0)
            ? ((w > 0) ? ring[w - 1][(NPR - 1) & (RING - 1)].y : NEGF)
            : sh1;
        const float n1 = cfin.y + lg2add(a1, a0);
        const float n0 = cfin.x + lg2add(a0, La1);
        a0 = n0; a1 = n1;
    }

    if (w == NW - 1 && lane == 24) g_final[b] = a1;  // u=199, t=2047
    #undef ISSUE
    #undef STOFF
}

// ---------------------------------------------------------------------------
// Kernel 3: loss = mean_b(-alpha_final[b]) in natural-log units.
// ---------------------------------------------------------------------------
__global__ void finish_kernel(float* __restrict__ out) {
    float s = 0.f;
    #pragma unroll
    for (int i = 0; i < Bb; i++) s += g_final[i];
    out[0] = -s * (LN2 / Bb);
}

__global__ void pad_kernel() { g_pad = 0; }

extern "C" void kernel_launch(void* const* d_in, const int* in_sizes, int n_in,
                              void* d_out, int out_size) {
    int ii = 0, ti = 1;
    if (n_in >= 2 && in_sizes[0] < in_sizes[1]) { ii = 1; ti = 0; }
    const float* inp = (const float*)d_in[ii];
    const int*   t32 = (const int*)d_in[ti];
    float* out = (float*)d_out;

    static int attr_done = 0;
    if (!attr_done) {
        cudaFuncSetAttribute(alpha_kernel,
                             cudaFuncAttributeMaxDynamicSharedMemorySize,
                             ST_FLOATS * (int)sizeof(float));
        attr_done = 1;
    }

    // ncu (-s 5 -c 1) lands on launch position 4 -> alpha_kernel.
    pad_kernel<<<1, 1>>>();
    lpt_kernel<<<Bb * Tt, 256>>>(inp, t32);
    wgt_kernel<<<dim3(NPR, Bb), 256>>>();
    alpha_kernel<<<Bb, 128, ST_FLOATS * sizeof(float)>>>();
    finish_kernel<<<1, 1>>>(out);
}